// round 1
// baseline (speedup 1.0000x reference)
#include <cuda_runtime.h>
#include <cstdint>

#define N_PTS   8192
#define DIM     128
#define BM      128
#define BN      128
#define NSPLIT  4
#define MARGIN  0.3f
#define BIGF    1e30f

// Scratch state (no device mallocs allowed)
__device__ int   g_mode;          // 1 if labels are int64 in memory, 0 if int32
__device__ int   g_lab[N_PTS];
__device__ float g_sq[N_PTS];
__device__ int   g_pos[N_PTS];    // float bits of hardest positive, init -1.0f
__device__ int   g_neg[N_PTS];    // float bits of hardest negative, init 1e30f

// ---------------------------------------------------------------------------
// Kernel 0: detect whether the label buffer is int64 or int32.
// If int64 (little-endian, values in [0,1024)), every odd int32 word is 0.
// Probability of false positive with int32 data: (1/1024)^64 ~ 0.
// ---------------------------------------------------------------------------
__global__ void detect_kernel(const int* __restrict__ l32) {
    if (threadIdx.x == 0) {
        int mode = 1;
        #pragma unroll 1
        for (int k = 0; k < 64; k++) {
            if (l32[2 * k + 1] != 0) { mode = 0; break; }
        }
        g_mode = mode;
    }
}

// ---------------------------------------------------------------------------
// Kernel 1: per-row squared norms, label conversion, sentinel init.
// One warp per row.
// ---------------------------------------------------------------------------
__global__ void prep_kernel(const float* __restrict__ emb,
                            const int*   __restrict__ l32) {
    int warp = (blockIdx.x * blockDim.x + threadIdx.x) >> 5;
    int lane = threadIdx.x & 31;
    if (warp >= N_PTS) return;
    const float4* row = (const float4*)(emb + (size_t)warp * DIM);
    float4 v = row[lane];                      // DIM/4 == 32, one float4 per lane
    float s = v.x * v.x + v.y * v.y + v.z * v.z + v.w * v.w;
    #pragma unroll
    for (int m = 16; m; m >>= 1) s += __shfl_xor_sync(0xFFFFFFFFu, s, m);
    if (lane == 0) {
        g_sq[warp]  = s;
        g_lab[warp] = g_mode ? l32[2 * warp] : l32[warp];
        g_pos[warp] = __float_as_int(-1.0f);
        g_neg[warp] = __float_as_int(BIGF);
    }
}

// ---------------------------------------------------------------------------
// Kernel 2: fused Gram tile + batch-hard mining.
// Block: 256 threads (16x16), tile BM x BN, K = DIM resident in shared.
// Shared layout is transposed [k][idx] so compute-side LDS is conflict-free.
// Grid: (N/BM) x NSPLIT; each block sweeps N/NSPLIT candidate columns.
// ---------------------------------------------------------------------------
extern __shared__ float smem[];

__global__ void __launch_bounds__(256, 1)
main_kernel(const float* __restrict__ emb) {
    float* As = smem;             // [DIM][BM]
    float* Bs = smem + BM * DIM;  // [DIM][BN]

    const int tid = threadIdx.x;
    const int tx  = tid & 15;     // column group
    const int ty  = tid >> 4;     // row group
    const int iBase = blockIdx.x * BM;

    // ---- Load A tile transposed. idx = c4*BM + row: lanes vary `row`,
    // so shared stores are conflict-free (consecutive words).
    for (int idx = tid; idx < BM * (DIM / 4); idx += 256) {
        int row = idx & (BM - 1);
        int c4  = idx >> 7;
        float4 v = *(const float4*)(emb + (size_t)(iBase + row) * DIM + c4 * 4);
        As[(c4 * 4 + 0) * BM + row] = v.x;
        As[(c4 * 4 + 1) * BM + row] = v.y;
        As[(c4 * 4 + 2) * BM + row] = v.z;
        As[(c4 * 4 + 3) * BM + row] = v.w;
    }

    // Per-thread row metadata (8 contiguous rows: ty*8 .. ty*8+7)
    int   rowi[8]; int labi[8]; float sqi[8];
    #pragma unroll
    for (int r = 0; r < 8; r++) {
        rowi[r] = iBase + ty * 8 + r;
        labi[r] = g_lab[rowi[r]];
        sqi[r]  = g_sq[rowi[r]];
    }

    float posv[8], negv[8];
    #pragma unroll
    for (int r = 0; r < 8; r++) { posv[r] = -1.0f; negv[r] = BIGF; }

    __syncthreads();   // A tile visible

    const int jSpan  = N_PTS / NSPLIT;          // 2048
    const int jStart = blockIdx.y * jSpan;

    for (int t = 0; t < jSpan / BN; t++) {      // 16 candidate tiles
        const int jBase = jStart + t * BN;

        // ---- Load B tile transposed (same pattern as A).
        for (int idx = tid; idx < BN * (DIM / 4); idx += 256) {
            int row = idx & (BN - 1);
            int c4  = idx >> 7;
            float4 v = *(const float4*)(emb + (size_t)(jBase + row) * DIM + c4 * 4);
            Bs[(c4 * 4 + 0) * BN + row] = v.x;
            Bs[(c4 * 4 + 1) * BN + row] = v.y;
            Bs[(c4 * 4 + 2) * BN + row] = v.z;
            Bs[(c4 * 4 + 3) * BN + row] = v.w;
        }
        __syncthreads();

        // Column metadata for this tile: columns tx + 16*c (strided so
        // b-operand LDS.32 across lanes is conflict-free).
        int labj[8]; float sqj[8];
        #pragma unroll
        for (int c = 0; c < 8; c++) {
            int j = jBase + tx + 16 * c;
            labj[c] = g_lab[j];
            sqj[c]  = g_sq[j];
        }

        float acc[8][8];
        #pragma unroll
        for (int r = 0; r < 8; r++)
            #pragma unroll
            for (int c = 0; c < 8; c++) acc[r][c] = 0.0f;

        #pragma unroll 4
        for (int k = 0; k < DIM; k++) {
            float4 a0 = *(const float4*)&As[k * BM + ty * 8];
            float4 a1 = *(const float4*)&As[k * BM + ty * 8 + 4];
            float a[8] = {a0.x, a0.y, a0.z, a0.w, a1.x, a1.y, a1.z, a1.w};
            float b[8];
            #pragma unroll
            for (int c = 0; c < 8; c++) b[c] = Bs[k * BN + tx + 16 * c];
            #pragma unroll
            for (int r = 0; r < 8; r++)
                #pragma unroll
                for (int c = 0; c < 8; c++)
                    acc[r][c] = fmaf(a[r], b[c], acc[r][c]);
        }

        // ---- Mining epilogue for this tile
        #pragma unroll
        for (int r = 0; r < 8; r++) {
            #pragma unroll
            for (int c = 0; c < 8; c++) {
                int j = jBase + tx + 16 * c;
                float d2 = sqi[r] + sqj[c] - 2.0f * acc[r][c];
                float dist = sqrtf(fmaxf(d2, 0.0f));
                if (j != rowi[r]) {
                    if (labj[c] == labi[r]) posv[r] = fmaxf(posv[r], dist);
                    else                    negv[r] = fminf(negv[r], dist);
                }
            }
        }
        __syncthreads();   // protect Bs before next tile load
    }

    // ---- Reduce across the 16 tx lanes (same ty) via shuffles, then atomics.
    #pragma unroll
    for (int r = 0; r < 8; r++) {
        float p = posv[r], n = negv[r];
        #pragma unroll
        for (int m = 8; m; m >>= 1) {
            p = fmaxf(p, __shfl_xor_sync(0xFFFFFFFFu, p, m));
            n = fminf(n, __shfl_xor_sync(0xFFFFFFFFu, n, m));
        }
        if (tx == 0) {
            // all candidate values >= 0 -> signed-int compare is order-correct
            atomicMax(&g_pos[rowi[r]], __float_as_int(p));
            atomicMin(&g_neg[rowi[r]], __float_as_int(n));
        }
    }
}

// ---------------------------------------------------------------------------
// Kernel 3: final reduction to scalar loss.
// ---------------------------------------------------------------------------
__global__ void final_kernel(float* __restrict__ out) {
    __shared__ float ssum[1024];
    __shared__ float scnt[1024];
    int tid = threadIdx.x;
    float s = 0.0f, c = 0.0f;
    for (int i = tid; i < N_PTS; i += 1024) {
        float p = __int_as_float(g_pos[i]);
        float n = __int_as_float(g_neg[i]);
        if (p >= 0.0f && n < 1e29f) {        // row has >=1 positive and negative
            s += fmaxf(p - n + MARGIN, 0.0f);
            c += 1.0f;
        }
    }
    ssum[tid] = s; scnt[tid] = c;
    __syncthreads();
    for (int m = 512; m; m >>= 1) {
        if (tid < m) { ssum[tid] += ssum[tid + m]; scnt[tid] += scnt[tid + m]; }
        __syncthreads();
    }
    if (tid == 0) out[0] = (scnt[0] > 0.0f) ? (ssum[0] / scnt[0]) : 0.0f;
}

// ---------------------------------------------------------------------------
extern "C" void kernel_launch(void* const* d_in, const int* in_sizes, int n_in,
                              void* d_out, int out_size) {
    const float* emb = (const float*)d_in[0];
    const int*   lab = (const int*)d_in[1];   // int32 view; width auto-detected

    const int smem_bytes = 2 * BM * DIM * (int)sizeof(float);  // 128 KB
    cudaFuncSetAttribute(main_kernel,
                         cudaFuncAttributeMaxDynamicSharedMemorySize,
                         smem_bytes);

    detect_kernel<<<1, 32>>>(lab);
    prep_kernel<<<N_PTS / 8, 256>>>(emb, lab);
    dim3 grid(N_PTS / BM, NSPLIT);
    main_kernel<<<grid, 256, smem_bytes>>>(emb);
    final_kernel<<<1, 1024>>>((float*)d_out);
}

// round 3
// speedup vs baseline: 2.1630x; 2.1630x over previous
#include <cuda_runtime.h>
#include <cuda_bf16.h>
#include <cstdint>

#define N_PTS   8192
#define DIM     128
#define BM      128
#define BN      128
#define NJ      2
#define JSPAN   (N_PTS / NJ)
#define TILES   (JSPAN / BN)      // 32
#define MARGIN  0.3f
#define BIGF    1e30f

// ---------------- device scratch ----------------
__device__ int   g_mode;
__device__ int   g_lab[N_PTS];
__device__ float g_sq[N_PTS];
__device__ int   g_pos[N_PTS];                       // float bits of hardest-pos d^2
__device__ int   g_neg[N_PTS];                       // float bits of hardest-neg d^2
__device__ __align__(256) unsigned short g_hi[N_PTS * DIM];
__device__ __align__(256) unsigned short g_lo[N_PTS * DIM];

// smem: A (hi 32K + lo 32K) @0, B double-buffer 2 x (hi 32K + lo 32K) @65536
#define SM_A      0
#define SM_B      65536
#define SM_TOTAL  196608

// ---------------- PTX helpers (all base sm_80+ ISA, no 'a' features) -------
__device__ __forceinline__ uint32_t smem_u32(const void* p) {
    uint32_t a;
    asm("{ .reg .u64 t; cvta.to.shared.u64 t, %1; cvt.u32.u64 %0, t; }" : "=r"(a) : "l"(p));
    return a;
}
__device__ __forceinline__ void cp_async16(uint32_t dst, const void* src) {
    asm volatile("cp.async.cg.shared.global [%0], [%1], 16;" :: "r"(dst), "l"(src) : "memory");
}
__device__ __forceinline__ void cp_commit() { asm volatile("cp.async.commit_group;" ::: "memory"); }
template <int N>
__device__ __forceinline__ void cp_wait() { asm volatile("cp.async.wait_group %0;" :: "n"(N) : "memory"); }

__device__ __forceinline__ void ldsm4(uint32_t* r, uint32_t addr) {
    asm volatile("ldmatrix.sync.aligned.m8n8.x4.shared.b16 {%0,%1,%2,%3}, [%4];"
                 : "=r"(r[0]), "=r"(r[1]), "=r"(r[2]), "=r"(r[3]) : "r"(addr));
}
__device__ __forceinline__ void mma_bf16(float* d, const uint32_t* a, uint32_t b0, uint32_t b1) {
    asm volatile("mma.sync.aligned.m16n8k16.row.col.f32.bf16.bf16.f32 "
                 "{%0,%1,%2,%3}, {%4,%5,%6,%7}, {%8,%9}, {%0,%1,%2,%3};"
                 : "+f"(d[0]), "+f"(d[1]), "+f"(d[2]), "+f"(d[3])
                 : "r"(a[0]), "r"(a[1]), "r"(a[2]), "r"(a[3]), "r"(b0), "r"(b1));
}

// ---------------- small kernels ----------------
__global__ void detect_kernel(const int* __restrict__ l32) {
    if (threadIdx.x == 0) {
        int mode = 1;
        #pragma unroll 1
        for (int k = 0; k < 64; k++)
            if (l32[2 * k + 1] != 0) { mode = 0; break; }
        g_mode = mode;
    }
}

__global__ void prep_kernel(const float* __restrict__ emb, const int* __restrict__ l32) {
    int warp = (blockIdx.x * blockDim.x + threadIdx.x) >> 5;
    int lane = threadIdx.x & 31;
    if (warp >= N_PTS) return;
    const float4* row = (const float4*)(emb + (size_t)warp * DIM);
    float4 v = row[lane];
    float s = v.x * v.x + v.y * v.y + v.z * v.z + v.w * v.w;
    #pragma unroll
    for (int m = 16; m; m >>= 1) s += __shfl_xor_sync(0xFFFFFFFFu, s, m);
    if (lane == 0) {
        g_sq[warp]  = s;
        g_lab[warp] = g_mode ? l32[2 * warp] : l32[warp];
        g_pos[warp] = __float_as_int(-1.0f);
        g_neg[warp] = __float_as_int(BIGF);
    }
}

__global__ void convert_kernel(const float* __restrict__ emb) {
    int i = blockIdx.x * blockDim.x + threadIdx.x;   // over N*DIM/2 float2 pairs
    float2 v = ((const float2*)emb)[i];
    __nv_bfloat16 hx = __float2bfloat16_rn(v.x);
    __nv_bfloat16 hy = __float2bfloat16_rn(v.y);
    __nv_bfloat16 lx = __float2bfloat16_rn(v.x - __bfloat162float(hx));
    __nv_bfloat16 ly = __float2bfloat16_rn(v.y - __bfloat162float(hy));
    ((ushort2*)g_hi)[i] = make_ushort2(__bfloat16_as_ushort(hx), __bfloat16_as_ushort(hy));
    ((ushort2*)g_lo)[i] = make_ushort2(__bfloat16_as_ushort(lx), __bfloat16_as_ushort(ly));
}

// ---------------- main fused GEMM + mining kernel ----------------
extern __shared__ unsigned char smem[];

// Load a 128-row tile (hi+lo bf16, swizzled [row][chunk^row&7]) via cp.async.
__device__ __forceinline__ void load_tile(uint32_t dst, int rowBase, int tid) {
    #pragma unroll
    for (int it = 0; it < 16; it++) {
        int u   = it * 256 + tid;
        int tau = u >> 11;                 // 0: hi, 1: lo
        int r   = (u >> 4) & 127;
        int c   = u & 15;                  // 16B chunk within 256B row
        const unsigned short* src = (tau ? g_lo : g_hi) + (size_t)(rowBase + r) * DIM + c * 8;
        cp_async16(dst + tau * 32768 + r * 256 + (((c ^ (r & 7))) << 4), src);
    }
}

__global__ void __launch_bounds__(256, 1) main_kernel() {
    const int tid  = threadIdx.x;
    const int lane = tid & 31;
    const int wid  = tid >> 5;
    const int wx   = wid & 3;              // n direction (4 warps x 32 cols)
    const int wy   = wid >> 2;             // m direction (2 warps x 64 rows)
    const int iBase  = blockIdx.x * BM;
    const int jStart = blockIdx.y * JSPAN;

    uint32_t sb    = smem_u32(smem);
    const uint32_t A_OFF = sb + SM_A;
    const uint32_t B_OFF = sb + SM_B;

    // ---- prologue: A (group), B0 (group), B1 (group)
    load_tile(A_OFF, iBase, tid);                 cp_commit();
    load_tile(B_OFF,          jStart,       tid); cp_commit();
    load_tile(B_OFF + 65536,  jStart + BN,  tid); cp_commit();

    // ---- per-lane ldmatrix address bases
    const int rsel = lane & 15;
    const int ksel = (lane >> 4) & 1;
    uint32_t aOff[4]; int a7[4];
    #pragma unroll
    for (int mb = 0; mb < 4; mb++) {
        int r = wy * 64 + mb * 16 + rsel;
        aOff[mb] = (uint32_t)(r * 256); a7[mb] = r & 7;
    }
    uint32_t bOff[2]; int b7[2];
    #pragma unroll
    for (int g = 0; g < 2; g++) {
        int n = wx * 32 + g * 16 + rsel;
        bOff[g] = (uint32_t)(n * 256); b7[g] = n & 7;
    }

    // ---- per-lane row metadata: rows iBase + wy*64 + mb*16 + (lane>>2) + h*8
    int   labi[8]; float sqi[8];
    #pragma unroll
    for (int mb = 0; mb < 4; mb++) {
        int r0 = iBase + wy * 64 + mb * 16 + (lane >> 2);
        labi[mb * 2 + 0] = g_lab[r0];     sqi[mb * 2 + 0] = g_sq[r0];
        labi[mb * 2 + 1] = g_lab[r0 + 8]; sqi[mb * 2 + 1] = g_sq[r0 + 8];
    }
    float pmm[8], nmm[8];                  // mining in m-space: m = sqj - 2*dot
    #pragma unroll
    for (int q = 0; q < 8; q++) { pmm[q] = -BIGF; nmm[q] = BIGF; }

    cp_wait<1>();                          // A + B0 resident
    __syncthreads();

    #pragma unroll 1
    for (int t = 0; t < TILES; t++) {
        const int jBase = jStart + t * BN;
        const uint32_t bufB = B_OFF + (t & 1) * 65536;

        // column metadata: cols jBase + wx*32 + nb*8 + (lane&3)*2 + {0,1}
        float sqjv[8]; int labjv[8];
        #pragma unroll
        for (int nb = 0; nb < 4; nb++) {
            int j0 = jBase + wx * 32 + nb * 8 + (lane & 3) * 2;
            sqjv[nb * 2 + 0] = g_sq[j0];     labjv[nb * 2 + 0] = g_lab[j0];
            sqjv[nb * 2 + 1] = g_sq[j0 + 1]; labjv[nb * 2 + 1] = g_lab[j0 + 1];
        }

        float acc[4][4][4];
        #pragma unroll
        for (int mb = 0; mb < 4; mb++)
            #pragma unroll
            for (int nb = 0; nb < 4; nb++)
                #pragma unroll
                for (int e = 0; e < 4; e++) acc[mb][nb][e] = 0.0f;

        // 3 products: (Ah,Bh), (Ah,Bl), (Al,Bh)
        #pragma unroll 1
        for (int p = 0; p < 3; p++) {
            uint32_t aT = A_OFF + ((p == 2) ? 32768u : 0u);
            uint32_t bT = bufB  + ((p == 1) ? 32768u : 0u);
            #pragma unroll
            for (int kc = 0; kc < 8; kc++) {
                int chunk = kc * 2 + ksel;
                uint32_t av[4][4];
                #pragma unroll
                for (int mb = 0; mb < 4; mb++)
                    ldsm4(av[mb], aT + aOff[mb] + ((chunk ^ a7[mb]) << 4));
                uint32_t bv[2][4];
                #pragma unroll
                for (int g = 0; g < 2; g++)
                    ldsm4(bv[g], bT + bOff[g] + ((chunk ^ b7[g]) << 4));
                #pragma unroll
                for (int mb = 0; mb < 4; mb++)
                    #pragma unroll
                    for (int g = 0; g < 2; g++) {
                        mma_bf16(acc[mb][g * 2 + 0], av[mb], bv[g][0], bv[g][2]);
                        mma_bf16(acc[mb][g * 2 + 1], av[mb], bv[g][1], bv[g][3]);
                    }
            }
        }

        // ---- mining epilogue (registers only)
        #pragma unroll
        for (int mb = 0; mb < 4; mb++)
            #pragma unroll
            for (int nb = 0; nb < 4; nb++) {
                float m00 = fmaf(acc[mb][nb][0], -2.0f, sqjv[nb * 2 + 0]);
                float m01 = fmaf(acc[mb][nb][1], -2.0f, sqjv[nb * 2 + 1]);
                float m10 = fmaf(acc[mb][nb][2], -2.0f, sqjv[nb * 2 + 0]);
                float m11 = fmaf(acc[mb][nb][3], -2.0f, sqjv[nb * 2 + 1]);
                int h0 = mb * 2, h1 = mb * 2 + 1;
                if (labjv[nb * 2 + 0] == labi[h0]) pmm[h0] = fmaxf(pmm[h0], m00);
                else                               nmm[h0] = fminf(nmm[h0], m00);
                if (labjv[nb * 2 + 1] == labi[h0]) pmm[h0] = fmaxf(pmm[h0], m01);
                else                               nmm[h0] = fminf(nmm[h0], m01);
                if (labjv[nb * 2 + 0] == labi[h1]) pmm[h1] = fmaxf(pmm[h1], m10);
                else                               nmm[h1] = fminf(nmm[h1], m10);
                if (labjv[nb * 2 + 1] == labi[h1]) pmm[h1] = fmaxf(pmm[h1], m11);
                else                               nmm[h1] = fminf(nmm[h1], m11);
            }

        __syncthreads();                    // everyone done reading B[t&1]
        if (t + 2 < TILES) {
            load_tile(B_OFF + (t & 1) * 65536, jStart + (t + 2) * BN, tid);
            cp_commit();
        }
        if (t + 1 < TILES) {
            if (t + 2 < TILES) cp_wait<1>(); else cp_wait<0>();
            __syncthreads();                // B[t+1] resident + visible
        }
    }

    // ---- reduce quads (lanes sharing l>>2 hold same rows) then atomics
    #pragma unroll
    for (int mb = 0; mb < 4; mb++) {
        #pragma unroll
        for (int h = 0; h < 2; h++) {
            int q = mb * 2 + h;
            float p = sqi[q] + pmm[q];      // hardest-pos d^2
            float n = sqi[q] + nmm[q];      // hardest-neg d^2
            p = fmaxf(p, __shfl_xor_sync(0xFFFFFFFFu, p, 1));
            p = fmaxf(p, __shfl_xor_sync(0xFFFFFFFFu, p, 2));
            n = fminf(n, __shfl_xor_sync(0xFFFFFFFFu, n, 1));
            n = fminf(n, __shfl_xor_sync(0xFFFFFFFFu, n, 2));
            if ((lane & 3) == 0) {
                int row = iBase + wy * 64 + mb * 16 + (lane >> 2) + h * 8;
                atomicMax(&g_pos[row], __float_as_int(p));
                atomicMin(&g_neg[row], __float_as_int(n));
            }
        }
    }
}

// ---------------- final reduction ----------------
__global__ void final_kernel(float* __restrict__ out) {
    __shared__ float ssum[1024];
    __shared__ float scnt[1024];
    int tid = threadIdx.x;
    float s = 0.0f, c = 0.0f;
    for (int i = tid; i < N_PTS; i += 1024) {
        float p = __int_as_float(g_pos[i]);    // hardest-pos d^2 (~0/neg if none)
        float n = __int_as_float(g_neg[i]);    // hardest-neg d^2 (1e30 if none)
        if (p > 1e-2f && n < 1e29f) {          // diag residual << 1e-2 << real d^2
            s += fmaxf(sqrtf(p) - sqrtf(fmaxf(n, 0.0f)) + MARGIN, 0.0f);
            c += 1.0f;
        }
    }
    ssum[tid] = s; scnt[tid] = c;
    __syncthreads();
    for (int m = 512; m; m >>= 1) {
        if (tid < m) { ssum[tid] += ssum[tid + m]; scnt[tid] += scnt[tid + m]; }
        __syncthreads();
    }
    if (tid == 0) out[0] = (scnt[0] > 0.0f) ? (ssum[0] / scnt[0]) : 0.0f;
}

// ---------------- launch ----------------
extern "C" void kernel_launch(void* const* d_in, const int* in_sizes, int n_in,
                              void* d_out, int out_size) {
    const float* emb = (const float*)d_in[0];
    const int*   lab = (const int*)d_in[1];

    cudaFuncSetAttribute(main_kernel, cudaFuncAttributeMaxDynamicSharedMemorySize, SM_TOTAL);

    detect_kernel<<<1, 32>>>(lab);
    prep_kernel<<<N_PTS * 32 / 256, 256>>>(emb, lab);
    convert_kernel<<<N_PTS * DIM / 2 / 256, 256>>>(emb);
    dim3 grid(N_PTS / BM, NJ);
    main_kernel<<<grid, 256, SM_TOTAL>>>();
    final_kernel<<<1, 1024>>>((float*)d_out);
}

// round 4
// speedup vs baseline: 3.4509x; 1.5954x over previous
#include <cuda_runtime.h>
#include <cuda_bf16.h>
#include <cstdint>

#define N_PTS   8192
#define DIM     128
#define BM      128
#define BN      128
#define NJ      2
#define JSPAN   (N_PTS / NJ)
#define TILES   (JSPAN / BN)      // 32
#define MARGIN  0.3f
#define BIGF    1e30f
#define NTHREADS 512

// ---------------- device scratch ----------------
__device__ int   g_mode;
__device__ __align__(128) int   g_lab[N_PTS];
__device__ __align__(128) float g_sq[N_PTS];
__device__ int   g_pos[N_PTS];                       // float bits of hardest-pos d^2
__device__ int   g_neg[N_PTS];                       // float bits of hardest-neg d^2
__device__ __align__(256) unsigned short g_hi[N_PTS * DIM];
__device__ __align__(256) unsigned short g_lo[N_PTS * DIM];

// smem bytes: A (hi+lo) @0 (64K), B double buffer @65536 (2x64K), meta @196608 (2x1K)
#define SM_A      0
#define SM_B      65536
#define SM_META   196608
#define SM_TOTAL  198656

// ---------------- PTX helpers (base sm_80+ ISA only) ----------------
__device__ __forceinline__ uint32_t smem_u32(const void* p) {
    uint32_t a;
    asm("{ .reg .u64 t; cvta.to.shared.u64 t, %1; cvt.u32.u64 %0, t; }" : "=r"(a) : "l"(p));
    return a;
}
__device__ __forceinline__ void cp_async16(uint32_t dst, const void* src) {
    asm volatile("cp.async.cg.shared.global [%0], [%1], 16;" :: "r"(dst), "l"(src) : "memory");
}
__device__ __forceinline__ void cp_commit() { asm volatile("cp.async.commit_group;" ::: "memory"); }
template <int N>
__device__ __forceinline__ void cp_wait() { asm volatile("cp.async.wait_group %0;" :: "n"(N) : "memory"); }

__device__ __forceinline__ void ldsm4(uint32_t* r, uint32_t addr) {
    asm volatile("ldmatrix.sync.aligned.m8n8.x4.shared.b16 {%0,%1,%2,%3}, [%4];"
                 : "=r"(r[0]), "=r"(r[1]), "=r"(r[2]), "=r"(r[3]) : "r"(addr));
}
__device__ __forceinline__ void mma_bf16(float* d, const uint32_t* a, uint32_t b0, uint32_t b1) {
    asm volatile("mma.sync.aligned.m16n8k16.row.col.f32.bf16.bf16.f32 "
                 "{%0,%1,%2,%3}, {%4,%5,%6,%7}, {%8,%9}, {%0,%1,%2,%3};"
                 : "+f"(d[0]), "+f"(d[1]), "+f"(d[2]), "+f"(d[3])
                 : "r"(a[0]), "r"(a[1]), "r"(a[2]), "r"(a[3]), "r"(b0), "r"(b1));
}

// ---------------- small kernels ----------------
__global__ void detect_kernel(const int* __restrict__ l32) {
    if (threadIdx.x == 0) {
        int mode = 1;
        #pragma unroll 1
        for (int k = 0; k < 64; k++)
            if (l32[2 * k + 1] != 0) { mode = 0; break; }
        g_mode = mode;
    }
}

__global__ void prep_kernel(const float* __restrict__ emb, const int* __restrict__ l32) {
    int warp = (blockIdx.x * blockDim.x + threadIdx.x) >> 5;
    int lane = threadIdx.x & 31;
    if (warp >= N_PTS) return;
    const float4* row = (const float4*)(emb + (size_t)warp * DIM);
    float4 v = row[lane];
    float s = v.x * v.x + v.y * v.y + v.z * v.z + v.w * v.w;
    #pragma unroll
    for (int m = 16; m; m >>= 1) s += __shfl_xor_sync(0xFFFFFFFFu, s, m);
    if (lane == 0) {
        g_sq[warp]  = s;
        g_lab[warp] = g_mode ? l32[2 * warp] : l32[warp];
        g_pos[warp] = __float_as_int(-1.0f);
        g_neg[warp] = __float_as_int(BIGF);
    }
}

__global__ void convert_kernel(const float* __restrict__ emb) {
    int i = blockIdx.x * blockDim.x + threadIdx.x;   // over N*DIM/2 float2 pairs
    float2 v = ((const float2*)emb)[i];
    __nv_bfloat16 hx = __float2bfloat16_rn(v.x);
    __nv_bfloat16 hy = __float2bfloat16_rn(v.y);
    __nv_bfloat16 lx = __float2bfloat16_rn(v.x - __bfloat162float(hx));
    __nv_bfloat16 ly = __float2bfloat16_rn(v.y - __bfloat162float(hy));
    ((ushort2*)g_hi)[i] = make_ushort2(__bfloat16_as_ushort(hx), __bfloat16_as_ushort(hy));
    ((ushort2*)g_lo)[i] = make_ushort2(__bfloat16_as_ushort(lx), __bfloat16_as_ushort(ly));
}

// ---------------- main fused GEMM + mining kernel ----------------
extern __shared__ unsigned char smem[];

// Load 128-row tile (hi+lo bf16, swizzle [row][chunk ^ (row&7)]); optionally meta.
__device__ __forceinline__ void load_tile(uint32_t dst, uint32_t metaDst, int rowBase, int tid) {
    #pragma unroll
    for (int it = 0; it < 8; it++) {
        int u   = it * NTHREADS + tid;
        int tau = u >> 11;                 // 0: hi, 1: lo
        int r   = (u >> 4) & 127;
        int c   = u & 15;                  // 16B chunk in 256B row
        const unsigned short* src = (tau ? g_lo : g_hi) + (size_t)(rowBase + r) * DIM + c * 8;
        cp_async16(dst + tau * 32768 + r * 256 + ((c ^ (r & 7)) << 4), src);
    }
    if (metaDst) {
        if (tid < 32)
            cp_async16(metaDst + tid * 16, (const char*)g_sq + (size_t)rowBase * 4 + tid * 16);
        else if (tid < 64)
            cp_async16(metaDst + 512 + (tid - 32) * 16, (const char*)g_lab + (size_t)rowBase * 4 + (tid - 32) * 16);
    }
}

__global__ void __launch_bounds__(NTHREADS, 1) main_kernel() {
    const int tid  = threadIdx.x;
    const int lane = tid & 31;
    const int wid  = tid >> 5;
    const int wx   = wid & 3;              // n: 4 warps x 32 cols
    const int wy   = wid >> 2;             // m: 4 warps x 32 rows
    const int iBase  = blockIdx.x * BM;
    const int jStart = blockIdx.y * JSPAN;

    uint32_t sb = smem_u32(smem);
    const uint32_t A_OFF = sb + SM_A;
    const uint32_t B_OFF = sb + SM_B;
    const uint32_t M_OFF = sb + SM_META;

    // prologue: A, B0(+meta), B1(+meta)
    load_tile(A_OFF, 0, iBase, tid);                        cp_commit();
    load_tile(B_OFF,         M_OFF,        jStart,      tid); cp_commit();
    load_tile(B_OFF + 65536, M_OFF + 1024, jStart + BN, tid); cp_commit();

    // ldmatrix bases
    const int rsel = lane & 15;
    const int ksel = (lane >> 4) & 1;
    uint32_t aAddr[2]; int a7[2];
    #pragma unroll
    for (int mb = 0; mb < 2; mb++) {
        int r = wy * 32 + mb * 16 + rsel;
        aAddr[mb] = A_OFF + (uint32_t)(r * 256); a7[mb] = r & 7;
    }
    uint32_t bOffs[2]; int b7[2];
    #pragma unroll
    for (int g = 0; g < 2; g++) {
        int n = wx * 32 + g * 16 + rsel;
        bOffs[g] = (uint32_t)(n * 256); b7[g] = n & 7;
    }

    // row metadata: rows iBase + wy*32 + mb*16 + (lane>>2) + h*8
    int labi[4]; float sqi[4]; float pmm[4], nmm[4];
    #pragma unroll
    for (int mb = 0; mb < 2; mb++) {
        int r0 = iBase + wy * 32 + mb * 16 + (lane >> 2);
        labi[mb * 2 + 0] = g_lab[r0];     sqi[mb * 2 + 0] = g_sq[r0];
        labi[mb * 2 + 1] = g_lab[r0 + 8]; sqi[mb * 2 + 1] = g_sq[r0 + 8];
        pmm[mb * 2] = -BIGF; pmm[mb * 2 + 1] = -BIGF;
        nmm[mb * 2] =  BIGF; nmm[mb * 2 + 1] =  BIGF;
    }

    cp_wait<1>();                          // A + B0 resident
    __syncthreads();

    #pragma unroll 1
    for (int t = 0; t < TILES; t++) {
        const uint32_t bufB  = B_OFF + (t & 1) * 65536;
        const unsigned char* metaS = smem + SM_META + (t & 1) * 1024;

        float acc[2][4][4];
        #pragma unroll
        for (int mb = 0; mb < 2; mb++)
            #pragma unroll
            for (int nb = 0; nb < 4; nb++)
                #pragma unroll
                for (int e = 0; e < 4; e++) acc[mb][nb][e] = 0.0f;

        #pragma unroll
        for (int kc = 0; kc < 8; kc++) {
            const int chunk = kc * 2 + ksel;
            uint32_t ah[2][4], al[2][4], bh[2][4], bl[2][4];
            #pragma unroll
            for (int mb = 0; mb < 2; mb++) {
                uint32_t off = (uint32_t)((chunk ^ a7[mb]) << 4);
                ldsm4(ah[mb], aAddr[mb] + off);
                ldsm4(al[mb], aAddr[mb] + 32768u + off);
            }
            #pragma unroll
            for (int g = 0; g < 2; g++) {
                uint32_t off = (uint32_t)((chunk ^ b7[g]) << 4);
                ldsm4(bh[g], bufB + bOffs[g] + off);
                ldsm4(bl[g], bufB + 32768u + bOffs[g] + off);
            }
            #pragma unroll
            for (int mb = 0; mb < 2; mb++)
                #pragma unroll
                for (int g = 0; g < 2; g++) {
                    mma_bf16(acc[mb][g * 2 + 0], ah[mb], bh[g][0], bh[g][2]);
                    mma_bf16(acc[mb][g * 2 + 1], ah[mb], bh[g][1], bh[g][3]);
                    mma_bf16(acc[mb][g * 2 + 0], ah[mb], bl[g][0], bl[g][2]);
                    mma_bf16(acc[mb][g * 2 + 1], ah[mb], bl[g][1], bl[g][3]);
                    mma_bf16(acc[mb][g * 2 + 0], al[mb], bh[g][0], bh[g][2]);
                    mma_bf16(acc[mb][g * 2 + 1], al[mb], bh[g][1], bh[g][3]);
                }
        }

        // column metadata from smem
        float2 sq2[4]; int2 lab2[4];
        #pragma unroll
        for (int nb = 0; nb < 4; nb++) {
            int idx = wx * 32 + nb * 8 + (lane & 3) * 2;     // even
            sq2[nb]  = *(const float2*)(metaS + idx * 4);
            lab2[nb] = *(const int2*)(metaS + 512 + idx * 4);
        }

        // mining epilogue (m-space: m = sqj - 2*dot)
        #pragma unroll
        for (int mb = 0; mb < 2; mb++)
            #pragma unroll
            for (int nb = 0; nb < 4; nb++) {
                float m00 = fmaf(acc[mb][nb][0], -2.0f, sq2[nb].x);
                float m01 = fmaf(acc[mb][nb][1], -2.0f, sq2[nb].y);
                float m10 = fmaf(acc[mb][nb][2], -2.0f, sq2[nb].x);
                float m11 = fmaf(acc[mb][nb][3], -2.0f, sq2[nb].y);
                int h0 = mb * 2, h1 = mb * 2 + 1;
                if (lab2[nb].x == labi[h0]) pmm[h0] = fmaxf(pmm[h0], m00);
                else                        nmm[h0] = fminf(nmm[h0], m00);
                if (lab2[nb].y == labi[h0]) pmm[h0] = fmaxf(pmm[h0], m01);
                else                        nmm[h0] = fminf(nmm[h0], m01);
                if (lab2[nb].x == labi[h1]) pmm[h1] = fmaxf(pmm[h1], m10);
                else                        nmm[h1] = fminf(nmm[h1], m10);
                if (lab2[nb].y == labi[h1]) pmm[h1] = fmaxf(pmm[h1], m11);
                else                        nmm[h1] = fminf(nmm[h1], m11);
            }

        __syncthreads();                   // done reading B[t&1] + meta[t&1]
        if (t + 2 < TILES) {
            load_tile(B_OFF + (t & 1) * 65536, M_OFF + (t & 1) * 1024,
                      jStart + (t + 2) * BN, tid);
            cp_commit();
        }
        if (t + 1 < TILES) {
            if (t + 2 < TILES) cp_wait<1>(); else cp_wait<0>();
            __syncthreads();               // B[t+1] resident + visible
        }
    }

    // quad-reduce (lanes sharing l>>2 hold same rows), then atomics
    #pragma unroll
    for (int mb = 0; mb < 2; mb++) {
        #pragma unroll
        for (int h = 0; h < 2; h++) {
            int q = mb * 2 + h;
            float p = sqi[q] + pmm[q];     // hardest-pos d^2
            float n = sqi[q] + nmm[q];     // hardest-neg d^2
            p = fmaxf(p, __shfl_xor_sync(0xFFFFFFFFu, p, 1));
            p = fmaxf(p, __shfl_xor_sync(0xFFFFFFFFu, p, 2));
            n = fminf(n, __shfl_xor_sync(0xFFFFFFFFu, n, 1));
            n = fminf(n, __shfl_xor_sync(0xFFFFFFFFu, n, 2));
            if ((lane & 3) == 0) {
                int row = iBase + wy * 32 + mb * 16 + (lane >> 2) + h * 8;
                atomicMax(&g_pos[row], __float_as_int(p));
                atomicMin(&g_neg[row], __float_as_int(n));
            }
        }
    }
}

// ---------------- final reduction ----------------
__global__ void final_kernel(float* __restrict__ out) {
    __shared__ float ssum[1024];
    __shared__ float scnt[1024];
    int tid = threadIdx.x;
    float s = 0.0f, c = 0.0f;
    for (int i = tid; i < N_PTS; i += 1024) {
        float p = __int_as_float(g_pos[i]);    // hardest-pos d^2
        float n = __int_as_float(g_neg[i]);    // hardest-neg d^2 (1e30 if none)
        if (p > 1e-2f && n < 1e29f) {          // diag residual << 1e-2 << real d^2
            s += fmaxf(sqrtf(p) - sqrtf(fmaxf(n, 0.0f)) + MARGIN, 0.0f);
            c += 1.0f;
        }
    }
    ssum[tid] = s; scnt[tid] = c;
    __syncthreads();
    for (int m = 512; m; m >>= 1) {
        if (tid < m) { ssum[tid] += ssum[tid + m]; scnt[tid] += scnt[tid + m]; }
        __syncthreads();
    }
    if (tid == 0) out[0] = (scnt[0] > 0.0f) ? (ssum[0] / scnt[0]) : 0.0f;
}

// ---------------- launch ----------------
extern "C" void kernel_launch(void* const* d_in, const int* in_sizes, int n_in,
                              void* d_out, int out_size) {
    const float* emb = (const float*)d_in[0];
    const int*   lab = (const int*)d_in[1];

    cudaFuncSetAttribute(main_kernel, cudaFuncAttributeMaxDynamicSharedMemorySize, SM_TOTAL);

    detect_kernel<<<1, 32>>>(lab);
    prep_kernel<<<N_PTS * 32 / 256, 256>>>(emb, lab);
    convert_kernel<<<N_PTS * DIM / 2 / 256, 256>>>(emb);
    dim3 grid(N_PTS / BM, NJ);
    main_kernel<<<grid, NTHREADS, SM_TOTAL>>>();
    final_kernel<<<1, 1024>>>((float*)d_out);
}

// round 5
// speedup vs baseline: 5.7147x; 1.6560x over previous
#include <cuda_runtime.h>
#include <cuda_bf16.h>
#include <cstdint>

#define N_PTS   8192
#define DIM     128
#define NTILE   64                 // 8192 / 128
#define TRI     ((NTILE * (NTILE + 1)) / 2)   // 2080 tile-pairs
#define GRID_MAIN 148
#define MARGIN  0.3f
#define BIGF    1e30f
#define NTHREADS 512

// ---------------- device scratch ----------------
__device__ int   g_mode;
__device__ __align__(128) int   g_lab[N_PTS];
__device__ __align__(128) float g_sq[N_PTS];
__device__ int   g_pos[N_PTS];                       // float bits of hardest-pos d^2
__device__ int   g_neg[N_PTS];                       // float bits of hardest-neg d^2
__device__ __align__(256) unsigned short g_hi[N_PTS * DIM];
__device__ __align__(256) unsigned short g_lo[N_PTS * DIM];

// smem bytes: A (hi+lo) @0 (64K), B double buffer @65536 (2x64K), meta @196608 (2x1K)
#define SM_A      0
#define SM_B      65536
#define SM_META   196608
#define SM_TOTAL  198656

// ---------------- PTX helpers (base sm_80+ ISA only) ----------------
__device__ __forceinline__ uint32_t smem_u32(const void* p) {
    uint32_t a;
    asm("{ .reg .u64 t; cvta.to.shared.u64 t, %1; cvt.u32.u64 %0, t; }" : "=r"(a) : "l"(p));
    return a;
}
__device__ __forceinline__ void cp_async16(uint32_t dst, const void* src) {
    asm volatile("cp.async.cg.shared.global [%0], [%1], 16;" :: "r"(dst), "l"(src) : "memory");
}
__device__ __forceinline__ void cp_commit() { asm volatile("cp.async.commit_group;" ::: "memory"); }
template <int N>
__device__ __forceinline__ void cp_wait() { asm volatile("cp.async.wait_group %0;" :: "n"(N) : "memory"); }

__device__ __forceinline__ void ldsm4(uint32_t* r, uint32_t addr) {
    asm volatile("ldmatrix.sync.aligned.m8n8.x4.shared.b16 {%0,%1,%2,%3}, [%4];"
                 : "=r"(r[0]), "=r"(r[1]), "=r"(r[2]), "=r"(r[3]) : "r"(addr));
}
__device__ __forceinline__ void mma_bf16(float* d, const uint32_t* a, uint32_t b0, uint32_t b1) {
    asm volatile("mma.sync.aligned.m16n8k16.row.col.f32.bf16.bf16.f32 "
                 "{%0,%1,%2,%3}, {%4,%5,%6,%7}, {%8,%9}, {%0,%1,%2,%3};"
                 : "+f"(d[0]), "+f"(d[1]), "+f"(d[2]), "+f"(d[3])
                 : "r"(a[0]), "r"(a[1]), "r"(a[2]), "r"(a[3]), "r"(b0), "r"(b1));
}

// ---------------- small kernels ----------------
__global__ void detect_kernel(const int* __restrict__ l32) {
    if (threadIdx.x == 0) {
        int mode = 1;
        #pragma unroll 1
        for (int k = 0; k < 64; k++)
            if (l32[2 * k + 1] != 0) { mode = 0; break; }
        g_mode = mode;
    }
}

// Merged: norms + labels + sentinels + hi/lo bf16 split (one pass over emb).
__global__ void prep_kernel(const float* __restrict__ emb, const int* __restrict__ l32) {
    int warp = (blockIdx.x * blockDim.x + threadIdx.x) >> 5;
    int lane = threadIdx.x & 31;
    const float4* row = (const float4*)(emb + (size_t)warp * DIM);
    float4 v = row[lane];
    float s = v.x * v.x + v.y * v.y + v.z * v.z + v.w * v.w;
    #pragma unroll
    for (int m = 16; m; m >>= 1) s += __shfl_xor_sync(0xFFFFFFFFu, s, m);

    __nv_bfloat16 h0 = __float2bfloat16_rn(v.x), h1 = __float2bfloat16_rn(v.y);
    __nv_bfloat16 h2 = __float2bfloat16_rn(v.z), h3 = __float2bfloat16_rn(v.w);
    __nv_bfloat16 l0 = __float2bfloat16_rn(v.x - __bfloat162float(h0));
    __nv_bfloat16 l1 = __float2bfloat16_rn(v.y - __bfloat162float(h1));
    __nv_bfloat16 l2 = __float2bfloat16_rn(v.z - __bfloat162float(h2));
    __nv_bfloat16 l3 = __float2bfloat16_rn(v.w - __bfloat162float(h3));
    ushort4 hv = make_ushort4(__bfloat16_as_ushort(h0), __bfloat16_as_ushort(h1),
                              __bfloat16_as_ushort(h2), __bfloat16_as_ushort(h3));
    ushort4 lv = make_ushort4(__bfloat16_as_ushort(l0), __bfloat16_as_ushort(l1),
                              __bfloat16_as_ushort(l2), __bfloat16_as_ushort(l3));
    ((ushort4*)(g_hi + (size_t)warp * DIM))[lane] = hv;
    ((ushort4*)(g_lo + (size_t)warp * DIM))[lane] = lv;

    if (lane == 0) {
        g_sq[warp]  = s;
        g_lab[warp] = g_mode ? l32[2 * warp] : l32[warp];
        g_pos[warp] = __float_as_int(-1.0f);
        g_neg[warp] = __float_as_int(BIGF);
    }
}

// ---------------- main fused GEMM + two-sided mining kernel ----------------
extern __shared__ unsigned char smem[];

__device__ __forceinline__ void load_tileA(uint32_t dst, int rowBase, int tid) {
    #pragma unroll
    for (int it = 0; it < 8; it++) {
        int u   = it * NTHREADS + tid;
        int tau = u >> 11;                 // 0: hi, 1: lo
        int r   = (u >> 4) & 127;
        int c   = u & 15;
        const unsigned short* src = (tau ? g_lo : g_hi) + (size_t)(rowBase + r) * DIM + c * 8;
        cp_async16(dst + tau * 32768 + r * 256 + ((c ^ (r & 7)) << 4), src);
    }
}
__device__ __forceinline__ void load_tileB(uint32_t dst, uint32_t metaDst, int rowBase, int tid) {
    load_tileA(dst, rowBase, tid);
    if (tid < 32)
        cp_async16(metaDst + tid * 16, (const char*)g_sq + (size_t)rowBase * 4 + tid * 16);
    else if (tid < 64)
        cp_async16(metaDst + 512 + (tid - 32) * 16, (const char*)g_lab + (size_t)rowBase * 4 + (tid - 32) * 16);
}

__global__ void __launch_bounds__(NTHREADS, 1) main_kernel() {
    const int tid  = threadIdx.x;
    const int lane = tid & 31;
    const int wid  = tid >> 5;
    const int wx   = wid & 3;              // n: 4 warps x 32 cols
    const int wy   = wid >> 2;             // m: 4 warps x 32 rows

    uint32_t sb = smem_u32(smem);
    const uint32_t A_OFF = sb + SM_A;
    const uint32_t B_OFF = sb + SM_B;
    const uint32_t M_OFF = sb + SM_META;

    // ldmatrix bases (position in tile only)
    const int rsel = lane & 15;
    const int ksel = (lane >> 4) & 1;
    uint32_t aAddr[2]; int a7[2];
    #pragma unroll
    for (int mb = 0; mb < 2; mb++) {
        int r = wy * 32 + mb * 16 + rsel;
        aAddr[mb] = A_OFF + (uint32_t)(r * 256); a7[mb] = r & 7;
    }
    uint32_t bOffs[2]; int b7[2];
    #pragma unroll
    for (int g = 0; g < 2; g++) {
        int n = wx * 32 + g * 16 + rsel;
        bOffs[g] = (uint32_t)(n * 256); b7[g] = n & 7;
    }

    // ---- triangular schedule: CTA gets tiles [start, end) of TRI, row-major
    const int start = (int)(((long)blockIdx.x * TRI) / gridDim.x);
    const int end   = (int)(((long)(blockIdx.x + 1) * TRI) / gridDim.x);
    int ti = 0, rem = start;
    while (rem >= NTILE - ti) { rem -= NTILE - ti; ti++; }
    int tj0 = ti + rem;
    int w = start;

    #pragma unroll 1
    while (w < end) {
        const int len   = min(NTILE - tj0, end - w);
        const int iBase = ti * 128;

        // row metadata + mining state for this segment
        int labi[4]; float sqi[4]; float pmm[4], nmm[4];
        #pragma unroll
        for (int mb = 0; mb < 2; mb++) {
            int r0 = iBase + wy * 32 + mb * 16 + (lane >> 2);
            labi[mb * 2 + 0] = g_lab[r0];     sqi[mb * 2 + 0] = g_sq[r0];
            labi[mb * 2 + 1] = g_lab[r0 + 8]; sqi[mb * 2 + 1] = g_sq[r0 + 8];
            pmm[mb * 2] = -BIGF; pmm[mb * 2 + 1] = -BIGF;
            nmm[mb * 2] =  BIGF; nmm[mb * 2 + 1] =  BIGF;
        }

        // segment prologue: A, B0(+meta), B1(+meta)
        load_tileA(A_OFF, iBase, tid);                              cp_commit();
        load_tileB(B_OFF,         M_OFF,        tj0 * 128, tid);    cp_commit();
        if (len > 1) load_tileB(B_OFF + 65536, M_OFF + 1024, (tj0 + 1) * 128, tid);
        cp_commit();
        cp_wait<1>();
        __syncthreads();

        #pragma unroll 1
        for (int t = 0; t < len; t++) {
            const uint32_t bufB = B_OFF + (t & 1) * 65536;
            const int jBase = (tj0 + t) * 128;

            float acc[2][4][4];
            #pragma unroll
            for (int mb = 0; mb < 2; mb++)
                #pragma unroll
                for (int nb = 0; nb < 4; nb++)
                    #pragma unroll
                    for (int e = 0; e < 4; e++) acc[mb][nb][e] = 0.0f;

            #pragma unroll
            for (int kc = 0; kc < 8; kc++) {
                const int chunk = kc * 2 + ksel;
                uint32_t ah[2][4], al[2][4], bh[2][4], bl[2][4];
                #pragma unroll
                for (int mb = 0; mb < 2; mb++) {
                    uint32_t off = (uint32_t)((chunk ^ a7[mb]) << 4);
                    ldsm4(ah[mb], aAddr[mb] + off);
                    ldsm4(al[mb], aAddr[mb] + 32768u + off);
                }
                #pragma unroll
                for (int g = 0; g < 2; g++) {
                    uint32_t off = (uint32_t)((chunk ^ b7[g]) << 4);
                    ldsm4(bh[g], bufB + bOffs[g] + off);
                    ldsm4(bl[g], bufB + 32768u + bOffs[g] + off);
                }
                #pragma unroll
                for (int mb = 0; mb < 2; mb++)
                    #pragma unroll
                    for (int g = 0; g < 2; g++) {
                        mma_bf16(acc[mb][g * 2 + 0], ah[mb], bh[g][0], bh[g][2]);
                        mma_bf16(acc[mb][g * 2 + 1], ah[mb], bh[g][1], bh[g][3]);
                        mma_bf16(acc[mb][g * 2 + 0], ah[mb], bl[g][0], bl[g][2]);
                        mma_bf16(acc[mb][g * 2 + 1], ah[mb], bl[g][1], bl[g][3]);
                        mma_bf16(acc[mb][g * 2 + 0], al[mb], bh[g][0], bh[g][2]);
                        mma_bf16(acc[mb][g * 2 + 1], al[mb], bh[g][1], bh[g][3]);
                    }
            }

            // meta -> regs before the barrier, so prefetch can start early
            const unsigned char* metaS = smem + SM_META + (t & 1) * 1024;
            float2 sq2[4]; int2 lab2[4];
            #pragma unroll
            for (int nb = 0; nb < 4; nb++) {
                int idx = wx * 32 + nb * 8 + (lane & 3) * 2;
                sq2[nb]  = *(const float2*)(metaS + idx * 4);
                lab2[nb] = *(const int2*)(metaS + 512 + idx * 4);
            }
            __syncthreads();               // all reads of B[t&1] + meta[t&1] done
            if (t + 2 < len) {
                load_tileB(B_OFF + (t & 1) * 65536, M_OFF + (t & 1) * 1024,
                           (tj0 + t + 2) * 128, tid);
                cp_commit();
            }

            // ---- two-sided mining epilogue (registers; overlaps cp.async)
            #pragma unroll
            for (int nb = 0; nb < 4; nb++) {
                float cp0 = -BIGF, cn0 = BIGF, cp1 = -BIGF, cn1 = BIGF;
                #pragma unroll
                for (int mb = 0; mb < 2; mb++) {
                    const int h0 = mb * 2, h1 = mb * 2 + 1;
                    float m00 = fmaf(acc[mb][nb][0], -2.0f, sq2[nb].x);
                    float m01 = fmaf(acc[mb][nb][1], -2.0f, sq2[nb].y);
                    float m10 = fmaf(acc[mb][nb][2], -2.0f, sq2[nb].x);
                    float m11 = fmaf(acc[mb][nb][3], -2.0f, sq2[nb].y);
                    bool e00 = (lab2[nb].x == labi[h0]);
                    bool e01 = (lab2[nb].y == labi[h0]);
                    bool e10 = (lab2[nb].x == labi[h1]);
                    bool e11 = (lab2[nb].y == labi[h1]);
                    // row side (m-space)
                    if (e00) pmm[h0] = fmaxf(pmm[h0], m00); else nmm[h0] = fminf(nmm[h0], m00);
                    if (e01) pmm[h0] = fmaxf(pmm[h0], m01); else nmm[h0] = fminf(nmm[h0], m01);
                    if (e10) pmm[h1] = fmaxf(pmm[h1], m10); else nmm[h1] = fminf(nmm[h1], m10);
                    if (e11) pmm[h1] = fmaxf(pmm[h1], m11); else nmm[h1] = fminf(nmm[h1], m11);
                    // column side (full d^2)
                    float d00 = m00 + sqi[h0], d01 = m01 + sqi[h0];
                    float d10 = m10 + sqi[h1], d11 = m11 + sqi[h1];
                    if (e00) cp0 = fmaxf(cp0, d00); else cn0 = fminf(cn0, d00);
                    if (e01) cp1 = fmaxf(cp1, d01); else cn1 = fminf(cn1, d01);
                    if (e10) cp0 = fmaxf(cp0, d10); else cn0 = fminf(cn0, d10);
                    if (e11) cp1 = fmaxf(cp1, d11); else cn1 = fminf(cn1, d11);
                }
                // reduce over the 8 lanes sharing these 2 columns
                #pragma unroll
                for (int m = 4; m <= 16; m <<= 1) {
                    cp0 = fmaxf(cp0, __shfl_xor_sync(0xFFFFFFFFu, cp0, m));
                    cn0 = fminf(cn0, __shfl_xor_sync(0xFFFFFFFFu, cn0, m));
                    cp1 = fmaxf(cp1, __shfl_xor_sync(0xFFFFFFFFu, cp1, m));
                    cn1 = fminf(cn1, __shfl_xor_sync(0xFFFFFFFFu, cn1, m));
                }
                if (lane < 4) {
                    int j0 = jBase + wx * 32 + nb * 8 + lane * 2;
                    atomicMax(&g_pos[j0],     __float_as_int(cp0));
                    atomicMin(&g_neg[j0],     __float_as_int(cn0));
                    atomicMax(&g_pos[j0 + 1], __float_as_int(cp1));
                    atomicMin(&g_neg[j0 + 1], __float_as_int(cn1));
                }
            }

            if (t + 1 < len) {
                if (t + 2 < len) cp_wait<1>(); else cp_wait<0>();
                __syncthreads();           // B[t+1] resident + visible
            }
        }

        // ---- flush row-side mining for this segment
        #pragma unroll
        for (int mb = 0; mb < 2; mb++) {
            #pragma unroll
            for (int h = 0; h < 2; h++) {
                int q = mb * 2 + h;
                float p = sqi[q] + pmm[q];
                float n = sqi[q] + nmm[q];
                p = fmaxf(p, __shfl_xor_sync(0xFFFFFFFFu, p, 1));
                p = fmaxf(p, __shfl_xor_sync(0xFFFFFFFFu, p, 2));
                n = fminf(n, __shfl_xor_sync(0xFFFFFFFFu, n, 1));
                n = fminf(n, __shfl_xor_sync(0xFFFFFFFFu, n, 2));
                if ((lane & 3) == 0) {
                    int row = iBase + wy * 32 + mb * 16 + (lane >> 2) + h * 8;
                    atomicMax(&g_pos[row], __float_as_int(p));
                    atomicMin(&g_neg[row], __float_as_int(n));
                }
            }
        }

        w += len; ti++; tj0 = ti;
    }
}

// ---------------- final reduction ----------------
__global__ void final_kernel(float* __restrict__ out) {
    __shared__ float ssum[32], scnt[32];
    int tid = threadIdx.x, lane = tid & 31, wrp = tid >> 5;
    float s = 0.0f, c = 0.0f;
    for (int i = tid; i < N_PTS; i += 1024) {
        float p = __int_as_float(g_pos[i]);
        float n = __int_as_float(g_neg[i]);
        if (p > 1e-2f && n < 1e29f) {
            s += fmaxf(sqrtf(p) - sqrtf(fmaxf(n, 0.0f)) + MARGIN, 0.0f);
            c += 1.0f;
        }
    }
    #pragma unroll
    for (int m = 16; m; m >>= 1) {
        s += __shfl_xor_sync(0xFFFFFFFFu, s, m);
        c += __shfl_xor_sync(0xFFFFFFFFu, c, m);
    }
    if (lane == 0) { ssum[wrp] = s; scnt[wrp] = c; }
    __syncthreads();
    if (wrp == 0) {
        s = ssum[lane]; c = scnt[lane];
        #pragma unroll
        for (int m = 16; m; m >>= 1) {
            s += __shfl_xor_sync(0xFFFFFFFFu, s, m);
            c += __shfl_xor_sync(0xFFFFFFFFu, c, m);
        }
        if (lane == 0) out[0] = (c > 0.0f) ? (s / c) : 0.0f;
    }
}

// ---------------- launch ----------------
extern "C" void kernel_launch(void* const* d_in, const int* in_sizes, int n_in,
                              void* d_out, int out_size) {
    const float* emb = (const float*)d_in[0];
    const int*   lab = (const int*)d_in[1];

    cudaFuncSetAttribute(main_kernel, cudaFuncAttributeMaxDynamicSharedMemorySize, SM_TOTAL);

    detect_kernel<<<1, 32>>>(lab);
    prep_kernel<<<N_PTS * 32 / 256, 256>>>(emb, lab);
    main_kernel<<<GRID_MAIN, NTHREADS, SM_TOTAL>>>();
    final_kernel<<<1, 1024>>>((float*)d_out);
}